// round 13
// baseline (speedup 1.0000x reference)
#include <cuda_runtime.h>
#include <cuda_fp16.h>
#include <cstdint>

#define NR 131072
#define DD 128
#define KK 1024
#define TM 128
#define PAD 136                 // fp16 elems per padded row (272 B)

typedef unsigned long long ull;

// ---------------- device scratch (static; no runtime alloc) ----------------
__device__ int   g_idx[NR];
__device__ float g_sums[KK * DD];      // [K][D] layout (for vector red)
__device__ float g_count[KK];
__device__ float g_lossb[256];
__device__ float g_eT[KK * DD];        // e^T [K][D] fp32
__device__ __half g_eThi[KK * DD];     // fp16(e - 0.5), [K][D]
__device__ float g_cnorm[KK];
__device__ int   g_nflag;
__device__ int   g_flag[NR];
__device__ ull   g_best[NR];

// ---------------- smem layout (bytes) ----------------
#define AHALF   34816            /* 128*PAD*2 */
#define SM_A    0                /* Ahi | Alo : 69632 */
#define SM_B0   69632            /* Bhi only  : 34816 */
#define SM_B1   104448
#define SM_CN   139264           /* 1024 fp32 */
#define SM_MG   143360           /* merge: 3*512 B */
#define SM_TOTAL 144896

#define TAU_D 0.005f             // flag threshold on D-gap (~8 sigma of x.e_lo error)

// ---------------- helpers ----------------
__device__ __forceinline__ uint32_t smem_u32(const void* p) {
    uint32_t a;
    asm("{ .reg .u64 t; cvta.to.shared.u64 t, %1; cvt.u32.u64 %0, t; }"
        : "=r"(a) : "l"(p));
    return a;
}
__device__ __forceinline__ void cp_async16(uint32_t dst, const void* src) {
    asm volatile("cp.async.cg.shared.global [%0], [%1], 16;"
                 :: "r"(dst), "l"(src) : "memory");
}
__device__ __forceinline__ void cp_commit() {
    asm volatile("cp.async.commit_group;" ::: "memory");
}
__device__ __forceinline__ void cp_wait0() {
    asm volatile("cp.async.wait_group 0;" ::: "memory");
}
__device__ __forceinline__ void red_v4(float* ptr, float a, float b, float c, float d) {
    asm volatile("red.global.add.v4.f32 [%0], {%1, %2, %3, %4};"
                 :: "l"(ptr), "f"(a), "f"(b), "f"(c), "f"(d) : "memory");
}
__device__ __forceinline__ void mma_f16(float& d0, float& d1, float& d2, float& d3,
                                        uint32_t a0, uint32_t a1, uint32_t a2, uint32_t a3,
                                        uint32_t b0, uint32_t b1) {
    asm volatile("mma.sync.aligned.m16n8k16.row.col.f32.f16.f16.f32 "
                 "{%0,%1,%2,%3}, {%4,%5,%6,%7}, {%8,%9}, {%0,%1,%2,%3};"
                 : "+f"(d0), "+f"(d1), "+f"(d2), "+f"(d3)
                 : "r"(a0), "r"(a1), "r"(a2), "r"(a3), "r"(b0), "r"(b1));
}

// ---------------- prep kernels ----------------
__global__ void zero_kernel() {
    int i = blockIdx.x * 256 + threadIdx.x;
    if (i < KK * DD) g_sums[i] = 0.f;
    if (i < KK)      g_count[i] = 0.f;
    if (i < 256)     g_lossb[i] = 0.f;
    if (i == 0)      g_nflag = 0;
}

// transpose + centered fp16 split fused
__global__ void transpose_kernel(const float* __restrict__ emb) {
    __shared__ float t[32][33];
    int kb = blockIdx.x * 32, db = blockIdx.y * 32;
    int tx = threadIdx.x, ty = threadIdx.y;
    #pragma unroll
    for (int r = ty; r < 32; r += 8)
        t[r][tx] = emb[(size_t)(db + r) * KK + kb + tx];
    __syncthreads();
    #pragma unroll
    for (int r = ty; r < 32; r += 8) {
        float v = t[tx][r];
        size_t o = (size_t)(kb + r) * DD + db + tx;
        g_eT[o] = v;
        g_eThi[o] = __float2half_rn(v - 0.5f);
    }
}

__global__ void cnorm_kernel(const float* __restrict__ emb) {
    int k = blockIdx.x * 256 + threadIdx.x;
    float s = 0.f;
    #pragma unroll 8
    for (int d = 0; d < DD; d++) {
        float e = emb[(size_t)d * KK + k];
        s = fmaf(e, e, s);
    }
    g_cnorm[k] = s;
}

// ---------------- HMMA fp16-split argmin (M_warp=32, N_warp=64) ----------------
// 8 warps = 4 row-groups x 2 N-halves. D = x.e' - cn/2; argmax D.
__global__ void __launch_bounds__(256, 1)
argmin_mma_kernel(const float* __restrict__ x) {
    extern __shared__ __align__(16) char smem[];
    const int tid = threadIdx.x;
    const int wid = tid >> 5, lane = tid & 31;
    const int g = lane >> 2, tg = lane & 3;
    const int rw = (wid & 3) * 32;          // rows rw..rw+31
    const int cb = (wid >> 2) * 64;         // codes cb..cb+63 within tile
    const int row0 = blockIdx.x * TM;
    const uint32_t sb = smem_u32(smem);

    // ---- A tile: load fp32 x, split to fp16 hi/lo, store padded ----
    #pragma unroll
    for (int it = 0; it < 8; it++) {
        int c = it * 256 + tid;            // 0..2047
        int r = c >> 4, c8 = c & 15;
        const float4* src = (const float4*)(x + (size_t)(row0 + r) * DD + c8 * 8);
        float4 a = src[0], b = src[1];
        float vals[8] = {a.x, a.y, a.z, a.w, b.x, b.y, b.z, b.w};
        unsigned hs[8], ls[8];
        #pragma unroll
        for (int j = 0; j < 8; j++) {
            __half hb = __float2half_rn(vals[j]);
            hs[j] = __half_as_ushort(hb);
            ls[j] = __half_as_ushort(__float2half_rn(vals[j] - __half2float(hb)));
        }
        uint4 ph, pl;
        ph.x = hs[0] | (hs[1] << 16); ph.y = hs[2] | (hs[3] << 16);
        ph.z = hs[4] | (hs[5] << 16); ph.w = hs[6] | (hs[7] << 16);
        pl.x = ls[0] | (ls[1] << 16); pl.y = ls[2] | (ls[3] << 16);
        pl.z = ls[4] | (ls[5] << 16); pl.w = ls[6] | (ls[7] << 16);
        int off = r * (PAD * 2) + c8 * 16;
        *(uint4*)(smem + SM_A + off)         = ph;
        *(uint4*)(smem + SM_A + AHALF + off) = pl;
    }
    // cnorm -> smem
    ((float4*)(smem + SM_CN))[tid] = ((const float4*)g_cnorm)[tid];

    // ---- B tile 0 via cp.async ----
    #pragma unroll
    for (int it = 0; it < 8; it++) {
        int i = it * 256 + tid;            // 0..2047
        int r = i >> 4, c8 = i & 15;
        const __half* src = g_eThi + (size_t)r * DD + c8 * 8;
        cp_async16(sb + SM_B0 + r * (PAD * 2) + c8 * 16, src);
    }
    cp_commit();
    cp_wait0();
    __syncthreads();

    // per-thread trackers for 4 rows: r = rf*2 + h -> row rw + rf*16 + h*8 + g
    float v1[4], v2[4]; int i1[4];
    #pragma unroll
    for (int r = 0; r < 4; r++) { v1[r] = -3.4e38f; v2[r] = -3.4e38f; i1[r] = 0; }
    const float* cns = (const float*)(smem + SM_CN);

    for (int t = 0; t < 8; t++) {
        const int cur = t & 1;
        if (t < 7) {
            int nb = cur ^ 1;
            #pragma unroll
            for (int it = 0; it < 8; it++) {
                int i = it * 256 + tid;
                int r = i >> 4, c8 = i & 15;
                const __half* src = g_eThi + (size_t)((t + 1) * 128 + r) * DD + c8 * 8;
                cp_async16(sb + (nb ? SM_B1 : SM_B0) + r * (PAD * 2) + c8 * 16, src);
            }
            cp_commit();
        }

        const char* Bhi = smem + (cur ? SM_B1 : SM_B0);
        const char* Ahi = smem + SM_A;
        const char* Alo = Ahi + AHALF;

        float acc[2][8][4];
        #pragma unroll
        for (int rf = 0; rf < 2; rf++)
            #pragma unroll
            for (int f = 0; f < 8; f++) {
                float c0 = -0.5f * cns[t * 128 + cb + f * 8 + tg * 2];
                float c1 = -0.5f * cns[t * 128 + cb + f * 8 + tg * 2 + 1];
                acc[rf][f][0] = c0; acc[rf][f][1] = c1;
                acc[rf][f][2] = c0; acc[rf][f][3] = c1;
            }

        #pragma unroll
        for (int k = 0; k < 8; k++) {
            int ca = k * 16 + tg * 2;
            uint32_t ah[2][4], al[2][4];
            #pragma unroll
            for (int rf = 0; rf < 2; rf++) {
                int oa0 = (rw + rf * 16 + g) * (PAD * 2) + ca * 2;
                int oa1 = (rw + rf * 16 + g + 8) * (PAD * 2) + ca * 2;
                ah[rf][0] = *(const uint32_t*)(Ahi + oa0);
                ah[rf][1] = *(const uint32_t*)(Ahi + oa1);
                ah[rf][2] = *(const uint32_t*)(Ahi + oa0 + 16);
                ah[rf][3] = *(const uint32_t*)(Ahi + oa1 + 16);
                al[rf][0] = *(const uint32_t*)(Alo + oa0);
                al[rf][1] = *(const uint32_t*)(Alo + oa1);
                al[rf][2] = *(const uint32_t*)(Alo + oa0 + 16);
                al[rf][3] = *(const uint32_t*)(Alo + oa1 + 16);
            }
            #pragma unroll
            for (int f = 0; f < 8; f++) {
                int ob = (cb + f * 8 + g) * (PAD * 2) + ca * 2;
                uint32_t bh0 = *(const uint32_t*)(Bhi + ob);
                uint32_t bh1 = *(const uint32_t*)(Bhi + ob + 16);
                #pragma unroll
                for (int rf = 0; rf < 2; rf++) {
                    mma_f16(acc[rf][f][0], acc[rf][f][1], acc[rf][f][2], acc[rf][f][3],
                            ah[rf][0], ah[rf][1], ah[rf][2], ah[rf][3], bh0, bh1);
                    mma_f16(acc[rf][f][0], acc[rf][f][1], acc[rf][f][2], acc[rf][f][3],
                            al[rf][0], al[rf][1], al[rf][2], al[rf][3], bh0, bh1);
                }
            }
        }

        #pragma unroll
        for (int rf = 0; rf < 2; rf++)
            #pragma unroll
            for (int f = 0; f < 8; f++) {
                int idx0 = t * 128 + cb + f * 8 + tg * 2;
                float d;
                d = acc[rf][f][0];
                if (d > v1[rf * 2]) { v2[rf * 2] = v1[rf * 2]; v1[rf * 2] = d; i1[rf * 2] = idx0; }
                else if (d > v2[rf * 2]) v2[rf * 2] = d;
                d = acc[rf][f][1];
                if (d > v1[rf * 2]) { v2[rf * 2] = v1[rf * 2]; v1[rf * 2] = d; i1[rf * 2] = idx0 + 1; }
                else if (d > v2[rf * 2]) v2[rf * 2] = d;
                d = acc[rf][f][2];
                if (d > v1[rf * 2 + 1]) { v2[rf * 2 + 1] = v1[rf * 2 + 1]; v1[rf * 2 + 1] = d; i1[rf * 2 + 1] = idx0; }
                else if (d > v2[rf * 2 + 1]) v2[rf * 2 + 1] = d;
                d = acc[rf][f][3];
                if (d > v1[rf * 2 + 1]) { v2[rf * 2 + 1] = v1[rf * 2 + 1]; v1[rf * 2 + 1] = d; i1[rf * 2 + 1] = idx0 + 1; }
                else if (d > v2[rf * 2 + 1]) v2[rf * 2 + 1] = d;
            }

        if (t < 7) cp_wait0();
        __syncthreads();
    }

    // reduce across the 4 tg-lanes sharing each row
    #pragma unroll
    for (int r = 0; r < 4; r++) {
        #pragma unroll
        for (int off = 2; off; off >>= 1) {
            float ov1 = __shfl_down_sync(0xffffffffu, v1[r], off, 4);
            int   oi1 = __shfl_down_sync(0xffffffffu, i1[r], off, 4);
            float ov2 = __shfl_down_sync(0xffffffffu, v2[r], off, 4);
            if (ov1 > v1[r] || (ov1 == v1[r] && oi1 < i1[r])) {
                v2[r] = fmaxf(v1[r], ov2); v1[r] = ov1; i1[r] = oi1;
            } else v2[r] = fmaxf(v2[r], ov1);
        }
    }

    // merge N-halves: warps 0-3 (codes 0-63) publish, warps 4-7 combine + emit
    float* mv1 = (float*)(smem + SM_MG);
    int*   mi1 = (int*)(smem + SM_MG + 512);
    float* mv2 = (float*)(smem + SM_MG + 1024);
    if ((wid >> 2) == 0 && tg == 0) {
        #pragma unroll
        for (int r = 0; r < 4; r++) {
            int lr = rw + (r >> 1) * 16 + (r & 1) * 8 + g;
            mv1[lr] = v1[r]; mi1[lr] = i1[r]; mv2[lr] = v2[r];
        }
    }
    __syncthreads();
    if ((wid >> 2) == 1 && tg == 0) {
        #pragma unroll
        for (int r = 0; r < 4; r++) {
            int lr = rw + (r >> 1) * 16 + (r & 1) * 8 + g;
            float av1 = mv1[lr]; int ai1 = mi1[lr]; float av2 = mv2[lr];
            float w1, w2; int wi;
            if (av1 > v1[r] || (av1 == v1[r] && ai1 < i1[r])) {
                w1 = av1; wi = ai1; w2 = fmaxf(av2, v1[r]);
            } else {
                w1 = v1[r]; wi = i1[r]; w2 = fmaxf(v2[r], av1);
            }
            int grow = row0 + lr;
            g_idx[grow] = wi;
            if (w1 - w2 < TAU_D) {
                int s = atomicAdd(&g_nflag, 1);
                g_flag[s] = grow; g_best[grow] = ~0ull;
            }
        }
    }
}

// ---------------- tiled exact fp32 rescore of flagged rows ----------------
__global__ void __launch_bounds__(256)
rescore_kernel(const float* __restrict__ x) {
    __shared__ float xs[32 * 128];
    __shared__ int rows[32];
    int tid = threadIdx.x;
    int nflag = min(g_nflag, NR);
    int ntask = ((nflag + 31) >> 5) << 3;
    for (int task = blockIdx.x; task < ntask; task += gridDim.x) {
        int chunk = task >> 3, kt = task & 7;
        int base = chunk * 32;
        int cnt = min(32, nflag - base);
        __syncthreads();
        if (tid < cnt) rows[tid] = g_flag[base + tid];
        __syncthreads();
        for (int i = tid; i < cnt * 32; i += 256)
            ((float4*)xs)[i] = *(const float4*)(x + (size_t)rows[i >> 5] * DD + (i & 31) * 4);
        __syncthreads();

        int code = kt * 128 + (tid & 127);
        int r0 = (tid >> 7) * 16;
        const float4* e4 = (const float4*)(g_eT + (size_t)code * DD);
        float cn = g_cnorm[code];
        float s[16];
        #pragma unroll
        for (int i = 0; i < 16; i++) s[i] = 0.f;
        #pragma unroll 4
        for (int d4 = 0; d4 < 32; d4++) {
            float4 e = e4[d4];
            const float4* xr = ((const float4*)xs) + r0 * 32 + d4;
            #pragma unroll
            for (int i = 0; i < 16; i++) {
                float4 xv = xr[i * 32];
                s[i] = fmaf(e.x, xv.x, s[i]);
                s[i] = fmaf(e.y, xv.y, s[i]);
                s[i] = fmaf(e.z, xv.z, s[i]);
                s[i] = fmaf(e.w, xv.w, s[i]);
            }
        }
        #pragma unroll
        for (int i = 0; i < 16; i++) {
            int r = r0 + i;
            if (r < cnt) {
                float dist = fmaf(-2.f, s[i], cn);
                unsigned u = __float_as_uint(dist);
                u ^= (u >> 31) ? 0xFFFFFFFFu : 0x80000000u;
                ull key = ((ull)u << 32) | (unsigned)code;
                atomicMin(&g_best[rows[r]], key);
            }
        }
    }
}

__global__ void fix_kernel() {
    int i = blockIdx.x * 256 + threadIdx.x;
    if (i < g_nflag && i < NR) {
        int row = g_flag[i];
        g_idx[row] = (int)(g_best[row] & 0xFFFFFFFFu);
    }
}

// ---------------- gather q_st, loss, segment sums (vector red) ----------------
__global__ void scatter_kernel(const float* __restrict__ x, float* __restrict__ outq) {
    int gid = blockIdx.x * 256 + threadIdx.x;
    int n = gid >> 5, dq = gid & 31, d0 = dq * 4;
    int k = g_idx[n];
    float4 xv = *(const float4*)(x + (size_t)n * DD + d0);
    float4 qv = *(const float4*)(g_eT + (size_t)k * DD + d0);
    float r0 = qv.x - xv.x, r1 = qv.y - xv.y, r2 = qv.z - xv.z, r3 = qv.w - xv.w;
    float4 o = make_float4(xv.x + r0, xv.y + r1, xv.z + r2, xv.w + r3);
    *(float4*)(outq + (size_t)n * DD + d0) = o;
    float ls = r0 * r0 + r1 * r1 + r2 * r2 + r3 * r3;

    red_v4(&g_sums[(size_t)k * DD + d0], xv.x, xv.y, xv.z, xv.w);
    if (dq == 0) atomicAdd(&g_count[k], 1.0f);

    __shared__ float wsum[8];
    #pragma unroll
    for (int off = 16; off; off >>= 1) ls += __shfl_down_sync(0xffffffffu, ls, off);
    if ((threadIdx.x & 31) == 0) wsum[threadIdx.x >> 5] = ls;
    __syncthreads();
    if (threadIdx.x < 8) {
        float t = wsum[threadIdx.x];
        #pragma unroll
        for (int off = 4; off; off >>= 1) t += __shfl_down_sync(0xffu, t, off);
        if (threadIdx.x == 0) atomicAdd(&g_lossb[blockIdx.x & 255], t);
    }
}

// ---------------- EMA finalize + loss ----------------
__global__ void finalize_kernel(const float* __restrict__ ema_count,
                                const float* __restrict__ emb_sum,
                                float* __restrict__ out, long long out_size) {
    long long base_q = (long long)NR * DD;
    if (out_size < base_q + 2LL * DD * KK + KK + 1) return;
    int i = blockIdx.x * 256 + threadIdx.x;
    float* out_emb  = out + base_q;
    float* out_cnt  = out_emb + DD * KK;
    float* out_sum  = out_cnt + KK;
    float* out_loss = out_sum + DD * KK;
    if (i < DD * KK) {
        int k = i & (KK - 1);
        int d = i >> 10;                    // i = d*KK + k
        float cnt = 0.15f * ema_count[k] + 0.85f * g_count[k];
        float s   = 0.15f * emb_sum[i]   + 0.85f * g_sums[(size_t)k * DD + d];
        out_sum[i] = s;
        out_emb[i] = s / fmaxf(cnt, 1e-5f);
    }
    if (i < KK) out_cnt[i] = 0.15f * ema_count[i] + 0.85f * g_count[i];
    if (i == 0) {
        float t = 0.f;
        for (int b = 0; b < 256; b++) t += g_lossb[b];
        *out_loss = t * (1.0f / ((float)NR * (float)DD));
    }
}

extern "C" void kernel_launch(void* const* d_in, const int* in_sizes, int n_in,
                              void* d_out, int out_size) {
    const float* x         = (const float*)d_in[0];
    const float* emb       = (const float*)d_in[1];
    const float* ema_count = (const float*)d_in[2];
    const float* emb_sum   = (const float*)d_in[3];
    float* out = (float*)d_out;

    cudaFuncSetAttribute(argmin_mma_kernel,
                         cudaFuncAttributeMaxDynamicSharedMemorySize, SM_TOTAL);

    zero_kernel<<<(KK * DD + 255) / 256, 256>>>();
    transpose_kernel<<<dim3(KK / 32, DD / 32), dim3(32, 8)>>>(emb);
    cnorm_kernel<<<KK / 256, 256>>>(emb);
    argmin_mma_kernel<<<NR / TM, 256, SM_TOTAL>>>(x);
    rescore_kernel<<<1024, 256>>>(x);
    fix_kernel<<<NR / 256, 256>>>();
    scatter_kernel<<<(NR * 32) / 256, 256>>>(x, out);
    finalize_kernel<<<(DD * KK + 255) / 256, 256>>>(ema_count, emb_sum, out,
                                                    (long long)out_size);
}

// round 14
// speedup vs baseline: 1.3552x; 1.3552x over previous
#include <cuda_runtime.h>
#include <cuda_fp16.h>
#include <cstdint>

#define NR 131072
#define DD 128
#define KK 1024
#define TM 64                   // rows per block (4 warps x 16 rows)
#define PAD 136                 // fp16 elems per padded row (272 B)

typedef unsigned long long ull;

// ---------------- device scratch (static; no runtime alloc) ----------------
__device__ int   g_idx[NR];
__device__ float g_sums[KK * DD];      // [K][D] layout (for vector red)
__device__ float g_count[KK];
__device__ float g_lossb[256];
__device__ float g_eT[KK * DD];        // e^T [K][D] fp32
__device__ __half g_eThi[KK * DD];     // fp16(e - 0.5), [K][D]
__device__ float g_cnorm[KK];
__device__ int   g_nflag;
__device__ int   g_flag[NR];
__device__ ull   g_best[NR];

// ---------------- smem layout (bytes) ----------------
#define AHALF   17408            /* 64*PAD*2 */
#define SM_A    0                /* Ahi | Alo : 34816 */
#define SM_B    34816            /* Bhi single buffer : 34816 */
#define SM_CN   69632            /* 1024 fp32 */
#define SM_TOTAL 73728

#define TAU_D 0.005f             // flag threshold on D-gap (~8 sigma of x.e_lo error)

// ---------------- helpers ----------------
__device__ __forceinline__ uint32_t smem_u32(const void* p) {
    uint32_t a;
    asm("{ .reg .u64 t; cvta.to.shared.u64 t, %1; cvt.u32.u64 %0, t; }"
        : "=r"(a) : "l"(p));
    return a;
}
__device__ __forceinline__ void cp_async16(uint32_t dst, const void* src) {
    asm volatile("cp.async.cg.shared.global [%0], [%1], 16;"
                 :: "r"(dst), "l"(src) : "memory");
}
__device__ __forceinline__ void cp_commit() {
    asm volatile("cp.async.commit_group;" ::: "memory");
}
__device__ __forceinline__ void cp_wait0() {
    asm volatile("cp.async.wait_group 0;" ::: "memory");
}
__device__ __forceinline__ void red_v4(float* ptr, float a, float b, float c, float d) {
    asm volatile("red.global.add.v4.f32 [%0], {%1, %2, %3, %4};"
                 :: "l"(ptr), "f"(a), "f"(b), "f"(c), "f"(d) : "memory");
}
__device__ __forceinline__ void mma_f16(float& d0, float& d1, float& d2, float& d3,
                                        uint32_t a0, uint32_t a1, uint32_t a2, uint32_t a3,
                                        uint32_t b0, uint32_t b1) {
    asm volatile("mma.sync.aligned.m16n8k16.row.col.f32.f16.f16.f32 "
                 "{%0,%1,%2,%3}, {%4,%5,%6,%7}, {%8,%9}, {%0,%1,%2,%3};"
                 : "+f"(d0), "+f"(d1), "+f"(d2), "+f"(d3)
                 : "r"(a0), "r"(a1), "r"(a2), "r"(a3), "r"(b0), "r"(b1));
}

// ---------------- prep kernels ----------------
__global__ void zero_kernel() {
    int i = blockIdx.x * 256 + threadIdx.x;
    if (i < KK * DD) g_sums[i] = 0.f;
    if (i < KK)      g_count[i] = 0.f;
    if (i < 256)     g_lossb[i] = 0.f;
    if (i == 0)      g_nflag = 0;
}

// transpose + centered fp16 split fused
__global__ void transpose_kernel(const float* __restrict__ emb) {
    __shared__ float t[32][33];
    int kb = blockIdx.x * 32, db = blockIdx.y * 32;
    int tx = threadIdx.x, ty = threadIdx.y;
    #pragma unroll
    for (int r = ty; r < 32; r += 8)
        t[r][tx] = emb[(size_t)(db + r) * KK + kb + tx];
    __syncthreads();
    #pragma unroll
    for (int r = ty; r < 32; r += 8) {
        float v = t[tx][r];
        size_t o = (size_t)(kb + r) * DD + db + tx;
        g_eT[o] = v;
        g_eThi[o] = __float2half_rn(v - 0.5f);
    }
}

__global__ void cnorm_kernel(const float* __restrict__ emb) {
    int k = blockIdx.x * 256 + threadIdx.x;
    float s = 0.f;
    #pragma unroll 8
    for (int d = 0; d < DD; d++) {
        float e = emb[(size_t)d * KK + k];
        s = fmaf(e, e, s);
    }
    g_cnorm[k] = s;
}

// ---------------- HMMA fp16-split argmin (128 thr, 3 blocks/SM) ----------------
// D = x.e' - cn/2 (acc init = -cn/2); argmin dist == argmax D (row consts drop).
__global__ void __launch_bounds__(128, 3)
argmin_mma_kernel(const float* __restrict__ x) {
    extern __shared__ __align__(16) char smem[];
    const int tid = threadIdx.x;
    const int wid = tid >> 5, lane = tid & 31;
    const int g = lane >> 2, tg = lane & 3;
    const int row0 = blockIdx.x * TM;
    const uint32_t sb = smem_u32(smem);

    // ---- A tile: load fp32 x, split to fp16 hi/lo, store padded ----
    #pragma unroll
    for (int it = 0; it < 8; it++) {
        int c = it * 128 + tid;            // 0..1023
        int r = c >> 4, c8 = c & 15;
        const float4* src = (const float4*)(x + (size_t)(row0 + r) * DD + c8 * 8);
        float4 a = src[0], b = src[1];
        float vals[8] = {a.x, a.y, a.z, a.w, b.x, b.y, b.z, b.w};
        unsigned hs[8], ls[8];
        #pragma unroll
        for (int j = 0; j < 8; j++) {
            __half hb = __float2half_rn(vals[j]);
            hs[j] = __half_as_ushort(hb);
            ls[j] = __half_as_ushort(__float2half_rn(vals[j] - __half2float(hb)));
        }
        uint4 ph, pl;
        ph.x = hs[0] | (hs[1] << 16); ph.y = hs[2] | (hs[3] << 16);
        ph.z = hs[4] | (hs[5] << 16); ph.w = hs[6] | (hs[7] << 16);
        pl.x = ls[0] | (ls[1] << 16); pl.y = ls[2] | (ls[3] << 16);
        pl.z = ls[4] | (ls[5] << 16); pl.w = ls[6] | (ls[7] << 16);
        int off = r * (PAD * 2) + c8 * 16;
        *(uint4*)(smem + SM_A + off)         = ph;
        *(uint4*)(smem + SM_A + AHALF + off) = pl;
    }
    // cnorm -> smem (1024 floats, 128 threads -> 2 float4 each)
    ((float4*)(smem + SM_CN))[tid]       = ((const float4*)g_cnorm)[tid];
    ((float4*)(smem + SM_CN))[tid + 128] = ((const float4*)g_cnorm)[tid + 128];

    // ---- B tile 0 via cp.async ----
    #pragma unroll
    for (int it = 0; it < 16; it++) {
        int i = it * 128 + tid;            // 0..2047
        int r = i >> 4, c8 = i & 15;
        const __half* src = g_eThi + (size_t)r * DD + c8 * 8;
        cp_async16(sb + SM_B + r * (PAD * 2) + c8 * 16, src);
    }
    cp_commit();
    cp_wait0();
    __syncthreads();

    float va1 = -3.4e38f, va2 = -3.4e38f, vb1 = -3.4e38f, vb2 = -3.4e38f;
    int ia1 = 0, ib1 = 0;
    const int rw = wid * 16;
    const float* cns = (const float*)(smem + SM_CN);

    for (int t = 0; t < 8; t++) {
        if (t > 0) {
            __syncthreads();   // all warps done reading previous B tile
            #pragma unroll
            for (int it = 0; it < 16; it++) {
                int i = it * 128 + tid;
                int r = i >> 4, c8 = i & 15;
                const __half* src = g_eThi + (size_t)(t * 128 + r) * DD + c8 * 8;
                cp_async16(sb + SM_B + r * (PAD * 2) + c8 * 16, src);
            }
            cp_commit();
            cp_wait0();
            __syncthreads();
        }

        const char* Bhi = smem + SM_B;
        const char* Ahi = smem + SM_A;
        const char* Alo = Ahi + AHALF;

        float acc[16][4];
        #pragma unroll
        for (int f = 0; f < 16; f++) {
            float c0 = -0.5f * cns[t * 128 + f * 8 + tg * 2];
            float c1 = -0.5f * cns[t * 128 + f * 8 + tg * 2 + 1];
            acc[f][0] = c0; acc[f][1] = c1; acc[f][2] = c0; acc[f][3] = c1;
        }

        #pragma unroll
        for (int k = 0; k < 8; k++) {
            int ca = k * 16 + tg * 2;
            int oa0 = (rw + g) * (PAD * 2) + ca * 2;
            int oa1 = (rw + g + 8) * (PAD * 2) + ca * 2;
            uint32_t ah0 = *(const uint32_t*)(Ahi + oa0);
            uint32_t ah1 = *(const uint32_t*)(Ahi + oa1);
            uint32_t ah2 = *(const uint32_t*)(Ahi + oa0 + 16);
            uint32_t ah3 = *(const uint32_t*)(Ahi + oa1 + 16);
            uint32_t al0 = *(const uint32_t*)(Alo + oa0);
            uint32_t al1 = *(const uint32_t*)(Alo + oa1);
            uint32_t al2 = *(const uint32_t*)(Alo + oa0 + 16);
            uint32_t al3 = *(const uint32_t*)(Alo + oa1 + 16);
            #pragma unroll
            for (int f = 0; f < 16; f++) {
                int ob = (f * 8 + g) * (PAD * 2) + ca * 2;
                uint32_t bh0 = *(const uint32_t*)(Bhi + ob);
                uint32_t bh1 = *(const uint32_t*)(Bhi + ob + 16);
                mma_f16(acc[f][0], acc[f][1], acc[f][2], acc[f][3],
                        ah0, ah1, ah2, ah3, bh0, bh1);
                mma_f16(acc[f][0], acc[f][1], acc[f][2], acc[f][3],
                        al0, al1, al2, al3, bh0, bh1);
            }
        }

        #pragma unroll
        for (int f = 0; f < 16; f++) {
            int idx0 = t * 128 + f * 8 + tg * 2;
            float d;
            d = acc[f][0];
            if (d > va1) { va2 = va1; va1 = d; ia1 = idx0; } else if (d > va2) va2 = d;
            d = acc[f][1];
            if (d > va1) { va2 = va1; va1 = d; ia1 = idx0 + 1; } else if (d > va2) va2 = d;
            d = acc[f][2];
            if (d > vb1) { vb2 = vb1; vb1 = d; ib1 = idx0; } else if (d > vb2) vb2 = d;
            d = acc[f][3];
            if (d > vb1) { vb2 = vb1; vb1 = d; ib1 = idx0 + 1; } else if (d > vb2) vb2 = d;
        }
    }

    // reduce across the 4 tg-lanes sharing each row
    #pragma unroll
    for (int off = 2; off; off >>= 1) {
        float ov1 = __shfl_down_sync(0xffffffffu, va1, off, 4);
        int   oi1 = __shfl_down_sync(0xffffffffu, ia1, off, 4);
        float ov2 = __shfl_down_sync(0xffffffffu, va2, off, 4);
        if (ov1 > va1 || (ov1 == va1 && oi1 < ia1)) {
            va2 = fmaxf(va1, ov2); va1 = ov1; ia1 = oi1;
        } else va2 = fmaxf(va2, ov1);
        ov1 = __shfl_down_sync(0xffffffffu, vb1, off, 4);
        oi1 = __shfl_down_sync(0xffffffffu, ib1, off, 4);
        ov2 = __shfl_down_sync(0xffffffffu, vb2, off, 4);
        if (ov1 > vb1 || (ov1 == vb1 && oi1 < ib1)) {
            vb2 = fmaxf(vb1, ov2); vb1 = ov1; ib1 = oi1;
        } else vb2 = fmaxf(vb2, ov1);
    }
    if (tg == 0) {
        int ra = row0 + rw + g, rb = ra + 8;
        g_idx[ra] = ia1;
        g_idx[rb] = ib1;
        if (va1 - va2 < TAU_D) {
            int s = atomicAdd(&g_nflag, 1); g_flag[s] = ra; g_best[ra] = ~0ull;
        }
        if (vb1 - vb2 < TAU_D) {
            int s = atomicAdd(&g_nflag, 1); g_flag[s] = rb; g_best[rb] = ~0ull;
        }
    }
}

// ---------------- tiled exact fp32 rescore of flagged rows ----------------
__global__ void __launch_bounds__(256)
rescore_kernel(const float* __restrict__ x) {
    __shared__ float xs[32 * 128];
    __shared__ int rows[32];
    int tid = threadIdx.x;
    int nflag = min(g_nflag, NR);
    int ntask = ((nflag + 31) >> 5) << 3;
    for (int task = blockIdx.x; task < ntask; task += gridDim.x) {
        int chunk = task >> 3, kt = task & 7;
        int base = chunk * 32;
        int cnt = min(32, nflag - base);
        __syncthreads();
        if (tid < cnt) rows[tid] = g_flag[base + tid];
        __syncthreads();
        for (int i = tid; i < cnt * 32; i += 256)
            ((float4*)xs)[i] = *(const float4*)(x + (size_t)rows[i >> 5] * DD + (i & 31) * 4);
        __syncthreads();

        int code = kt * 128 + (tid & 127);
        int r0 = (tid >> 7) * 16;
        const float4* e4 = (const float4*)(g_eT + (size_t)code * DD);
        float cn = g_cnorm[code];
        float s[16];
        #pragma unroll
        for (int i = 0; i < 16; i++) s[i] = 0.f;
        #pragma unroll 4
        for (int d4 = 0; d4 < 32; d4++) {
            float4 e = e4[d4];
            const float4* xr = ((const float4*)xs) + r0 * 32 + d4;
            #pragma unroll
            for (int i = 0; i < 16; i++) {
                float4 xv = xr[i * 32];
                s[i] = fmaf(e.x, xv.x, s[i]);
                s[i] = fmaf(e.y, xv.y, s[i]);
                s[i] = fmaf(e.z, xv.z, s[i]);
                s[i] = fmaf(e.w, xv.w, s[i]);
            }
        }
        #pragma unroll
        for (int i = 0; i < 16; i++) {
            int r = r0 + i;
            if (r < cnt) {
                float dist = fmaf(-2.f, s[i], cn);
                unsigned u = __float_as_uint(dist);
                u ^= (u >> 31) ? 0xFFFFFFFFu : 0x80000000u;
                ull key = ((ull)u << 32) | (unsigned)code;
                atomicMin(&g_best[rows[r]], key);
            }
        }
    }
}

__global__ void fix_kernel() {
    int i = blockIdx.x * 256 + threadIdx.x;
    if (i < g_nflag && i < NR) {
        int row = g_flag[i];
        g_idx[row] = (int)(g_best[row] & 0xFFFFFFFFu);
    }
}

// ---------------- gather q_st, loss, segment sums (vector red) ----------------
__global__ void scatter_kernel(const float* __restrict__ x, float* __restrict__ outq) {
    int gid = blockIdx.x * 256 + threadIdx.x;
    int n = gid >> 5, dq = gid & 31, d0 = dq * 4;
    int k = g_idx[n];
    float4 xv = *(const float4*)(x + (size_t)n * DD + d0);
    float4 qv = *(const float4*)(g_eT + (size_t)k * DD + d0);
    float r0 = qv.x - xv.x, r1 = qv.y - xv.y, r2 = qv.z - xv.z, r3 = qv.w - xv.w;
    float4 o = make_float4(xv.x + r0, xv.y + r1, xv.z + r2, xv.w + r3);
    *(float4*)(outq + (size_t)n * DD + d0) = o;
    float ls = r0 * r0 + r1 * r1 + r2 * r2 + r3 * r3;

    red_v4(&g_sums[(size_t)k * DD + d0], xv.x, xv.y, xv.z, xv.w);
    if (dq == 0) atomicAdd(&g_count[k], 1.0f);

    __shared__ float wsum[8];
    #pragma unroll
    for (int off = 16; off; off >>= 1) ls += __shfl_down_sync(0xffffffffu, ls, off);
    if ((threadIdx.x & 31) == 0) wsum[threadIdx.x >> 5] = ls;
    __syncthreads();
    if (threadIdx.x < 8) {
        float t = wsum[threadIdx.x];
        #pragma unroll
        for (int off = 4; off; off >>= 1) t += __shfl_down_sync(0xffu, t, off);
        if (threadIdx.x == 0) atomicAdd(&g_lossb[blockIdx.x & 255], t);
    }
}

// ---------------- EMA finalize + loss ----------------
__global__ void finalize_kernel(const float* __restrict__ ema_count,
                                const float* __restrict__ emb_sum,
                                float* __restrict__ out, long long out_size) {
    long long base_q = (long long)NR * DD;
    if (out_size < base_q + 2LL * DD * KK + KK + 1) return;
    int i = blockIdx.x * 256 + threadIdx.x;
    float* out_emb  = out + base_q;
    float* out_cnt  = out_emb + DD * KK;
    float* out_sum  = out_cnt + KK;
    float* out_loss = out_sum + DD * KK;
    if (i < DD * KK) {
        int k = i & (KK - 1);
        int d = i >> 10;                    // i = d*KK + k
        float cnt = 0.15f * ema_count[k] + 0.85f * g_count[k];
        float s   = 0.15f * emb_sum[i]   + 0.85f * g_sums[(size_t)k * DD + d];
        out_sum[i] = s;
        out_emb[i] = s / fmaxf(cnt, 1e-5f);
    }
    if (i < KK) out_cnt[i] = 0.15f * ema_count[i] + 0.85f * g_count[i];
    if (i == 0) {
        float t = 0.f;
        for (int b = 0; b < 256; b++) t += g_lossb[b];
        *out_loss = t * (1.0f / ((float)NR * (float)DD));
    }
}

extern "C" void kernel_launch(void* const* d_in, const int* in_sizes, int n_in,
                              void* d_out, int out_size) {
    const float* x         = (const float*)d_in[0];
    const float* emb       = (const float*)d_in[1];
    const float* ema_count = (const float*)d_in[2];
    const float* emb_sum   = (const float*)d_in[3];
    float* out = (float*)d_out;

    cudaFuncSetAttribute(argmin_mma_kernel,
                         cudaFuncAttributeMaxDynamicSharedMemorySize, SM_TOTAL);

    zero_kernel<<<(KK * DD + 255) / 256, 256>>>();
    transpose_kernel<<<dim3(KK / 32, DD / 32), dim3(32, 8)>>>(emb);
    cnorm_kernel<<<KK / 256, 256>>>(emb);
    argmin_mma_kernel<<<NR / TM, 128, SM_TOTAL>>>(x);
    rescore_kernel<<<1024, 256>>>(x);
    fix_kernel<<<NR / 256, 256>>>();
    scatter_kernel<<<(NR * 32) / 256, 256>>>(x, out);
    finalize_kernel<<<(DD * KK + 255) / 256, 256>>>(ema_count, emb_sum, out,
                                                    (long long)out_size);
}

// round 15
// speedup vs baseline: 1.3689x; 1.0101x over previous
#include <cuda_runtime.h>
#include <cuda_fp16.h>
#include <cstdint>

#define NR 131072
#define DD 128
#define KK 1024
#define TM 64                   // rows per block (4 warps x 16 rows)
#define PAD 136                 // fp16 elems per padded row (272 B)

typedef unsigned long long ull;

// ---------------- device scratch (static; no runtime alloc) ----------------
__device__ int   g_idx[NR];
__device__ float g_sums[KK * DD];      // [K][D] layout (for vector red)
__device__ float g_count[KK];
__device__ float g_lossb[256];
__device__ float g_eT[KK * DD];        // e^T [K][D] fp32
__device__ __half g_eThi[KK * DD];     // fp16(e - 0.5), [K][D]
__device__ float g_cnorm[KK];
__device__ int   g_nflag;
__device__ int   g_flag[NR];
__device__ ull   g_best[NR];

// ---------------- smem layout (bytes) ----------------
#define AHALF   17408            /* 64*PAD*2 */
#define SM_A    0                /* Ahi | Alo : 34816 */
#define SM_B    34816            /* Bhi half-tile (64 codes) : 17408 */
#define SM_CN   52224            /* 1024 fp32 : 4096 */
#define SM_TOTAL 56320

#define TAU_D 0.005f             // flag threshold on D-gap (~8 sigma of x.e_lo error)

// ---------------- helpers ----------------
__device__ __forceinline__ uint32_t smem_u32(const void* p) {
    uint32_t a;
    asm("{ .reg .u64 t; cvta.to.shared.u64 t, %1; cvt.u32.u64 %0, t; }"
        : "=r"(a) : "l"(p));
    return a;
}
__device__ __forceinline__ void cp_async16(uint32_t dst, const void* src) {
    asm volatile("cp.async.cg.shared.global [%0], [%1], 16;"
                 :: "r"(dst), "l"(src) : "memory");
}
__device__ __forceinline__ void cp_commit() {
    asm volatile("cp.async.commit_group;" ::: "memory");
}
__device__ __forceinline__ void cp_wait0() {
    asm volatile("cp.async.wait_group 0;" ::: "memory");
}
__device__ __forceinline__ void red_v4(float* ptr, float a, float b, float c, float d) {
    asm volatile("red.global.add.v4.f32 [%0], {%1, %2, %3, %4};"
                 :: "l"(ptr), "f"(a), "f"(b), "f"(c), "f"(d) : "memory");
}
__device__ __forceinline__ void mma_f16(float& d0, float& d1, float& d2, float& d3,
                                        uint32_t a0, uint32_t a1, uint32_t a2, uint32_t a3,
                                        uint32_t b0, uint32_t b1) {
    asm volatile("mma.sync.aligned.m16n8k16.row.col.f32.f16.f16.f32 "
                 "{%0,%1,%2,%3}, {%4,%5,%6,%7}, {%8,%9}, {%0,%1,%2,%3};"
                 : "+f"(d0), "+f"(d1), "+f"(d2), "+f"(d3)
                 : "r"(a0), "r"(a1), "r"(a2), "r"(a3), "r"(b0), "r"(b1));
}

// ---------------- prep kernels ----------------
__global__ void zero_kernel() {
    int i = blockIdx.x * 256 + threadIdx.x;
    if (i < KK * DD) g_sums[i] = 0.f;
    if (i < KK)      g_count[i] = 0.f;
    if (i < 256)     g_lossb[i] = 0.f;
    if (i == 0)      g_nflag = 0;
}

// transpose + centered fp16 split fused
__global__ void transpose_kernel(const float* __restrict__ emb) {
    __shared__ float t[32][33];
    int kb = blockIdx.x * 32, db = blockIdx.y * 32;
    int tx = threadIdx.x, ty = threadIdx.y;
    #pragma unroll
    for (int r = ty; r < 32; r += 8)
        t[r][tx] = emb[(size_t)(db + r) * KK + kb + tx];
    __syncthreads();
    #pragma unroll
    for (int r = ty; r < 32; r += 8) {
        float v = t[tx][r];
        size_t o = (size_t)(kb + r) * DD + db + tx;
        g_eT[o] = v;
        g_eThi[o] = __float2half_rn(v - 0.5f);
    }
}

__global__ void cnorm_kernel(const float* __restrict__ emb) {
    int k = blockIdx.x * 256 + threadIdx.x;
    float s = 0.f;
    #pragma unroll 8
    for (int d = 0; d < DD; d++) {
        float e = emb[(size_t)d * KK + k];
        s = fmaf(e, e, s);
    }
    g_cnorm[k] = s;
}

// ---------------- HMMA fp16-split argmin (128 thr, 4 blocks/SM, N-halves) ----------------
// D = x.e' - cn/2 (acc init = -cn/2); argmin dist == argmax D (row consts drop).
__global__ void __launch_bounds__(128, 4)
argmin_mma_kernel(const float* __restrict__ x) {
    extern __shared__ __align__(16) char smem[];
    const int tid = threadIdx.x;
    const int wid = tid >> 5, lane = tid & 31;
    const int g = lane >> 2, tg = lane & 3;
    const int row0 = blockIdx.x * TM;
    const uint32_t sb = smem_u32(smem);

    // ---- A tile: load fp32 x, split to fp16 hi/lo, store padded ----
    #pragma unroll
    for (int it = 0; it < 8; it++) {
        int c = it * 128 + tid;            // 0..1023
        int r = c >> 4, c8 = c & 15;
        const float4* src = (const float4*)(x + (size_t)(row0 + r) * DD + c8 * 8);
        float4 a = src[0], b = src[1];
        float vals[8] = {a.x, a.y, a.z, a.w, b.x, b.y, b.z, b.w};
        unsigned hs[8], ls[8];
        #pragma unroll
        for (int j = 0; j < 8; j++) {
            __half hb = __float2half_rn(vals[j]);
            hs[j] = __half_as_ushort(hb);
            ls[j] = __half_as_ushort(__float2half_rn(vals[j] - __half2float(hb)));
        }
        uint4 ph, pl;
        ph.x = hs[0] | (hs[1] << 16); ph.y = hs[2] | (hs[3] << 16);
        ph.z = hs[4] | (hs[5] << 16); ph.w = hs[6] | (hs[7] << 16);
        pl.x = ls[0] | (ls[1] << 16); pl.y = ls[2] | (ls[3] << 16);
        pl.z = ls[4] | (ls[5] << 16); pl.w = ls[6] | (ls[7] << 16);
        int off = r * (PAD * 2) + c8 * 16;
        *(uint4*)(smem + SM_A + off)         = ph;
        *(uint4*)(smem + SM_A + AHALF + off) = pl;
    }
    // cnorm -> smem (1024 floats, 128 threads -> 2 float4 each)
    ((float4*)(smem + SM_CN))[tid]       = ((const float4*)g_cnorm)[tid];
    ((float4*)(smem + SM_CN))[tid + 128] = ((const float4*)g_cnorm)[tid + 128];

    // ---- B half-tile 0 (codes 0..63) via cp.async ----
    #pragma unroll
    for (int it = 0; it < 8; it++) {
        int i = it * 128 + tid;            // 0..1023
        int r = i >> 4, c8 = i & 15;
        const __half* src = g_eThi + (size_t)r * DD + c8 * 8;
        cp_async16(sb + SM_B + r * (PAD * 2) + c8 * 16, src);
    }
    cp_commit();
    cp_wait0();
    __syncthreads();

    float va1 = -3.4e38f, va2 = -3.4e38f, vb1 = -3.4e38f, vb2 = -3.4e38f;
    int ia1 = 0, ib1 = 0;
    const int rw = wid * 16;
    const float* cns = (const float*)(smem + SM_CN);

    for (int th = 0; th < 16; th++) {      // 8 k-tiles x 2 N-halves
        if (th > 0) {
            __syncthreads();   // all warps done reading previous half-tile
            #pragma unroll
            for (int it = 0; it < 8; it++) {
                int i = it * 128 + tid;
                int r = i >> 4, c8 = i & 15;
                const __half* src = g_eThi + (size_t)(th * 64 + r) * DD + c8 * 8;
                cp_async16(sb + SM_B + r * (PAD * 2) + c8 * 16, src);
            }
            cp_commit();
            cp_wait0();
            __syncthreads();
        }

        const char* Bhi = smem + SM_B;
        const char* Ahi = smem + SM_A;
        const char* Alo = Ahi + AHALF;
        const int code0 = th * 64;         // global code base of this half-tile

        float acc[8][4];
        #pragma unroll
        for (int f = 0; f < 8; f++) {
            float c0 = -0.5f * cns[code0 + f * 8 + tg * 2];
            float c1 = -0.5f * cns[code0 + f * 8 + tg * 2 + 1];
            acc[f][0] = c0; acc[f][1] = c1; acc[f][2] = c0; acc[f][3] = c1;
        }

        #pragma unroll
        for (int k = 0; k < 8; k++) {
            int ca = k * 16 + tg * 2;
            int oa0 = (rw + g) * (PAD * 2) + ca * 2;
            int oa1 = (rw + g + 8) * (PAD * 2) + ca * 2;
            uint32_t ah0 = *(const uint32_t*)(Ahi + oa0);
            uint32_t ah1 = *(const uint32_t*)(Ahi + oa1);
            uint32_t ah2 = *(const uint32_t*)(Ahi + oa0 + 16);
            uint32_t ah3 = *(const uint32_t*)(Ahi + oa1 + 16);
            uint32_t al0 = *(const uint32_t*)(Alo + oa0);
            uint32_t al1 = *(const uint32_t*)(Alo + oa1);
            uint32_t al2 = *(const uint32_t*)(Alo + oa0 + 16);
            uint32_t al3 = *(const uint32_t*)(Alo + oa1 + 16);
            #pragma unroll
            for (int f = 0; f < 8; f++) {
                int ob = (f * 8 + g) * (PAD * 2) + ca * 2;
                uint32_t bh0 = *(const uint32_t*)(Bhi + ob);
                uint32_t bh1 = *(const uint32_t*)(Bhi + ob + 16);
                mma_f16(acc[f][0], acc[f][1], acc[f][2], acc[f][3],
                        ah0, ah1, ah2, ah3, bh0, bh1);
                mma_f16(acc[f][0], acc[f][1], acc[f][2], acc[f][3],
                        al0, al1, al2, al3, bh0, bh1);
            }
        }

        #pragma unroll
        for (int f = 0; f < 8; f++) {
            int idx0 = code0 + f * 8 + tg * 2;
            float d;
            d = acc[f][0];
            if (d > va1) { va2 = va1; va1 = d; ia1 = idx0; } else if (d > va2) va2 = d;
            d = acc[f][1];
            if (d > va1) { va2 = va1; va1 = d; ia1 = idx0 + 1; } else if (d > va2) va2 = d;
            d = acc[f][2];
            if (d > vb1) { vb2 = vb1; vb1 = d; ib1 = idx0; } else if (d > vb2) vb2 = d;
            d = acc[f][3];
            if (d > vb1) { vb2 = vb1; vb1 = d; ib1 = idx0 + 1; } else if (d > vb2) vb2 = d;
        }
    }

    // reduce across the 4 tg-lanes sharing each row
    #pragma unroll
    for (int off = 2; off; off >>= 1) {
        float ov1 = __shfl_down_sync(0xffffffffu, va1, off, 4);
        int   oi1 = __shfl_down_sync(0xffffffffu, ia1, off, 4);
        float ov2 = __shfl_down_sync(0xffffffffu, va2, off, 4);
        if (ov1 > va1 || (ov1 == va1 && oi1 < ia1)) {
            va2 = fmaxf(va1, ov2); va1 = ov1; ia1 = oi1;
        } else va2 = fmaxf(va2, ov1);
        ov1 = __shfl_down_sync(0xffffffffu, vb1, off, 4);
        oi1 = __shfl_down_sync(0xffffffffu, ib1, off, 4);
        ov2 = __shfl_down_sync(0xffffffffu, vb2, off, 4);
        if (ov1 > vb1 || (ov1 == vb1 && oi1 < ib1)) {
            vb2 = fmaxf(vb1, ov2); vb1 = ov1; ib1 = oi1;
        } else vb2 = fmaxf(vb2, ov1);
    }
    if (tg == 0) {
        int ra = row0 + rw + g, rb = ra + 8;
        g_idx[ra] = ia1;
        g_idx[rb] = ib1;
        if (va1 - va2 < TAU_D) {
            int s = atomicAdd(&g_nflag, 1); g_flag[s] = ra; g_best[ra] = ~0ull;
        }
        if (vb1 - vb2 < TAU_D) {
            int s = atomicAdd(&g_nflag, 1); g_flag[s] = rb; g_best[rb] = ~0ull;
        }
    }
}

// ---------------- tiled exact fp32 rescore of flagged rows ----------------
__global__ void __launch_bounds__(256)
rescore_kernel(const float* __restrict__ x) {
    __shared__ float xs[32 * 128];
    __shared__ int rows[32];
    int tid = threadIdx.x;
    int nflag = min(g_nflag, NR);
    int ntask = ((nflag + 31) >> 5) << 3;
    for (int task = blockIdx.x; task < ntask; task += gridDim.x) {
        int chunk = task >> 3, kt = task & 7;
        int base = chunk * 32;
        int cnt = min(32, nflag - base);
        __syncthreads();
        if (tid < cnt) rows[tid] = g_flag[base + tid];
        __syncthreads();
        for (int i = tid; i < cnt * 32; i += 256)
            ((float4*)xs)[i] = *(const float4*)(x + (size_t)rows[i >> 5] * DD + (i & 31) * 4);
        __syncthreads();

        int code = kt * 128 + (tid & 127);
        int r0 = (tid >> 7) * 16;
        const float4* e4 = (const float4*)(g_eT + (size_t)code * DD);
        float cn = g_cnorm[code];
        float s[16];
        #pragma unroll
        for (int i = 0; i < 16; i++) s[i] = 0.f;
        #pragma unroll 4
        for (int d4 = 0; d4 < 32; d4++) {
            float4 e = e4[d4];
            const float4* xr = ((const float4*)xs) + r0 * 32 + d4;
            #pragma unroll
            for (int i = 0; i < 16; i++) {
                float4 xv = xr[i * 32];
                s[i] = fmaf(e.x, xv.x, s[i]);
                s[i] = fmaf(e.y, xv.y, s[i]);
                s[i] = fmaf(e.z, xv.z, s[i]);
                s[i] = fmaf(e.w, xv.w, s[i]);
            }
        }
        #pragma unroll
        for (int i = 0; i < 16; i++) {
            int r = r0 + i;
            if (r < cnt) {
                float dist = fmaf(-2.f, s[i], cn);
                unsigned u = __float_as_uint(dist);
                u ^= (u >> 31) ? 0xFFFFFFFFu : 0x80000000u;
                ull key = ((ull)u << 32) | (unsigned)code;
                atomicMin(&g_best[rows[r]], key);
            }
        }
    }
}

__global__ void fix_kernel() {
    int i = blockIdx.x * 256 + threadIdx.x;
    if (i < g_nflag && i < NR) {
        int row = g_flag[i];
        g_idx[row] = (int)(g_best[row] & 0xFFFFFFFFu);
    }
}

// ---------------- gather q_st, loss, segment sums (vector red) ----------------
__global__ void scatter_kernel(const float* __restrict__ x, float* __restrict__ outq) {
    int gid = blockIdx.x * 256 + threadIdx.x;
    int n = gid >> 5, dq = gid & 31, d0 = dq * 4;
    int k = g_idx[n];
    float4 xv = *(const float4*)(x + (size_t)n * DD + d0);
    float4 qv = *(const float4*)(g_eT + (size_t)k * DD + d0);
    float r0 = qv.x - xv.x, r1 = qv.y - xv.y, r2 = qv.z - xv.z, r3 = qv.w - xv.w;
    float4 o = make_float4(xv.x + r0, xv.y + r1, xv.z + r2, xv.w + r3);
    *(float4*)(outq + (size_t)n * DD + d0) = o;
    float ls = r0 * r0 + r1 * r1 + r2 * r2 + r3 * r3;

    red_v4(&g_sums[(size_t)k * DD + d0], xv.x, xv.y, xv.z, xv.w);
    if (dq == 0) atomicAdd(&g_count[k], 1.0f);

    __shared__ float wsum[8];
    #pragma unroll
    for (int off = 16; off; off >>= 1) ls += __shfl_down_sync(0xffffffffu, ls, off);
    if ((threadIdx.x & 31) == 0) wsum[threadIdx.x >> 5] = ls;
    __syncthreads();
    if (threadIdx.x < 8) {
        float t = wsum[threadIdx.x];
        #pragma unroll
        for (int off = 4; off; off >>= 1) t += __shfl_down_sync(0xffu, t, off);
        if (threadIdx.x == 0) atomicAdd(&g_lossb[blockIdx.x & 255], t);
    }
}

// ---------------- EMA finalize + loss ----------------
__global__ void finalize_kernel(const float* __restrict__ ema_count,
                                const float* __restrict__ emb_sum,
                                float* __restrict__ out, long long out_size) {
    long long base_q = (long long)NR * DD;
    if (out_size < base_q + 2LL * DD * KK + KK + 1) return;
    int i = blockIdx.x * 256 + threadIdx.x;
    float* out_emb  = out + base_q;
    float* out_cnt  = out_emb + DD * KK;
    float* out_sum  = out_cnt + KK;
    float* out_loss = out_sum + DD * KK;
    if (i < DD * KK) {
        int k = i & (KK - 1);
        int d = i >> 10;                    // i = d*KK + k
        float cnt = 0.15f * ema_count[k] + 0.85f * g_count[k];
        float s   = 0.15f * emb_sum[i]   + 0.85f * g_sums[(size_t)k * DD + d];
        out_sum[i] = s;
        out_emb[i] = s / fmaxf(cnt, 1e-5f);
    }
    if (i < KK) out_cnt[i] = 0.15f * ema_count[i] + 0.85f * g_count[i];
    if (i == 0) {
        float t = 0.f;
        for (int b = 0; b < 256; b++) t += g_lossb[b];
        *out_loss = t * (1.0f / ((float)NR * (float)DD));
    }
}

extern "C" void kernel_launch(void* const* d_in, const int* in_sizes, int n_in,
                              void* d_out, int out_size) {
    const float* x         = (const float*)d_in[0];
    const float* emb       = (const float*)d_in[1];
    const float* ema_count = (const float*)d_in[2];
    const float* emb_sum   = (const float*)d_in[3];
    float* out = (float*)d_out;

    cudaFuncSetAttribute(argmin_mma_kernel,
                         cudaFuncAttributeMaxDynamicSharedMemorySize, SM_TOTAL);

    zero_kernel<<<(KK * DD + 255) / 256, 256>>>();
    transpose_kernel<<<dim3(KK / 32, DD / 32), dim3(32, 8)>>>(emb);
    cnorm_kernel<<<KK / 256, 256>>>(emb);
    argmin_mma_kernel<<<NR / TM, 128, SM_TOTAL>>>(x);
    rescore_kernel<<<1024, 256>>>(x);
    fix_kernel<<<NR / 256, 256>>>();
    scatter_kernel<<<(NR * 32) / 256, 256>>>(x, out);
    finalize_kernel<<<(DD * KK + 255) / 256, 256>>>(ema_count, emb_sum, out,
                                                    (long long)out_size);
}

// round 16
// speedup vs baseline: 1.6395x; 1.1977x over previous
#include <cuda_runtime.h>
#include <cuda_fp16.h>
#include <cstdint>

#define NR 131072
#define DD 128
#define KK 1024
#define TM 64                   // rows per block (4 warps x 16 rows)
#define PAD 136                 // fp16 elems per padded row (272 B)

typedef unsigned long long ull;

// ---------------- device scratch (static; no runtime alloc) ----------------
__device__ int   g_idx[NR];
__device__ float g_sums[KK * DD];      // [K][D] layout (for vector red)
__device__ float g_count[KK];
__device__ float g_lossb[256];
__device__ float g_eT[KK * DD];        // e^T [K][D] fp32
__device__ __half g_eThi[KK * DD];     // fp16(e - 0.5), [K][D]
__device__ float g_cnorm[KK];
__device__ int   g_nflag;
__device__ int   g_flag[NR];
__device__ ull   g_best[NR];

// ---------------- smem layout (bytes) ----------------
#define ABYTES  17408            /* 64*PAD*2 (hi only) */
#define SM_A    0                /* Ahi : 17408 */
#define SM_B    17408            /* Bhi half-tile (64 codes) : 17408 */
#define SM_CN   34816            /* 1024 fp32 : 4096 */
#define SM_TOTAL 38912

#define TAU_D 0.009f             // flag threshold on D-gap (~9 sigma of x_lo.e'_hi error)

// ---------------- helpers ----------------
__device__ __forceinline__ uint32_t smem_u32(const void* p) {
    uint32_t a;
    asm("{ .reg .u64 t; cvta.to.shared.u64 t, %1; cvt.u32.u64 %0, t; }"
        : "=r"(a) : "l"(p));
    return a;
}
__device__ __forceinline__ void cp_async16(uint32_t dst, const void* src) {
    asm volatile("cp.async.cg.shared.global [%0], [%1], 16;"
                 :: "r"(dst), "l"(src) : "memory");
}
__device__ __forceinline__ void cp_commit() {
    asm volatile("cp.async.commit_group;" ::: "memory");
}
__device__ __forceinline__ void cp_wait0() {
    asm volatile("cp.async.wait_group 0;" ::: "memory");
}
__device__ __forceinline__ void red_v4(float* ptr, float a, float b, float c, float d) {
    asm volatile("red.global.add.v4.f32 [%0], {%1, %2, %3, %4};"
                 :: "l"(ptr), "f"(a), "f"(b), "f"(c), "f"(d) : "memory");
}
__device__ __forceinline__ void mma_f16(float& d0, float& d1, float& d2, float& d3,
                                        uint32_t a0, uint32_t a1, uint32_t a2, uint32_t a3,
                                        uint32_t b0, uint32_t b1) {
    asm volatile("mma.sync.aligned.m16n8k16.row.col.f32.f16.f16.f32 "
                 "{%0,%1,%2,%3}, {%4,%5,%6,%7}, {%8,%9}, {%0,%1,%2,%3};"
                 : "+f"(d0), "+f"(d1), "+f"(d2), "+f"(d3)
                 : "r"(a0), "r"(a1), "r"(a2), "r"(a3), "r"(b0), "r"(b1));
}

// ---------------- prep kernels ----------------
__global__ void zero_kernel() {
    int i = blockIdx.x * 256 + threadIdx.x;
    if (i < KK * DD) g_sums[i] = 0.f;
    if (i < KK)      g_count[i] = 0.f;
    if (i < 256)     g_lossb[i] = 0.f;
    if (i == 0)      g_nflag = 0;
}

// transpose + centered fp16 split fused
__global__ void transpose_kernel(const float* __restrict__ emb) {
    __shared__ float t[32][33];
    int kb = blockIdx.x * 32, db = blockIdx.y * 32;
    int tx = threadIdx.x, ty = threadIdx.y;
    #pragma unroll
    for (int r = ty; r < 32; r += 8)
        t[r][tx] = emb[(size_t)(db + r) * KK + kb + tx];
    __syncthreads();
    #pragma unroll
    for (int r = ty; r < 32; r += 8) {
        float v = t[tx][r];
        size_t o = (size_t)(kb + r) * DD + db + tx;
        g_eT[o] = v;
        g_eThi[o] = __float2half_rn(v - 0.5f);
    }
}

__global__ void cnorm_kernel(const float* __restrict__ emb) {
    int k = blockIdx.x * 256 + threadIdx.x;
    float s = 0.f;
    #pragma unroll 8
    for (int d = 0; d < DD; d++) {
        float e = emb[(size_t)d * KK + k];
        s = fmaf(e, e, s);
    }
    g_cnorm[k] = s;
}

// ---------------- HMMA fp16 1-pass argmin (128 thr, 5 blocks/SM, N-halves) ----------------
// D = xhi.e' - cn/2 (acc init = -cn/2); argmin dist == argmax D (row consts drop).
__global__ void __launch_bounds__(128, 5)
argmin_mma_kernel(const float* __restrict__ x) {
    extern __shared__ __align__(16) char smem[];
    const int tid = threadIdx.x;
    const int wid = tid >> 5, lane = tid & 31;
    const int g = lane >> 2, tg = lane & 3;
    const int row0 = blockIdx.x * TM;
    const uint32_t sb = smem_u32(smem);

    // ---- A tile: load fp32 x, round to fp16, store padded (hi only) ----
    #pragma unroll
    for (int it = 0; it < 8; it++) {
        int c = it * 128 + tid;            // 0..1023
        int r = c >> 4, c8 = c & 15;
        const float4* src = (const float4*)(x + (size_t)(row0 + r) * DD + c8 * 8);
        float4 a = src[0], b = src[1];
        float vals[8] = {a.x, a.y, a.z, a.w, b.x, b.y, b.z, b.w};
        unsigned hs[8];
        #pragma unroll
        for (int j = 0; j < 8; j++)
            hs[j] = __half_as_ushort(__float2half_rn(vals[j]));
        uint4 ph;
        ph.x = hs[0] | (hs[1] << 16); ph.y = hs[2] | (hs[3] << 16);
        ph.z = hs[4] | (hs[5] << 16); ph.w = hs[6] | (hs[7] << 16);
        int off = r * (PAD * 2) + c8 * 16;
        *(uint4*)(smem + SM_A + off) = ph;
    }
    // cnorm -> smem (1024 floats, 128 threads -> 2 float4 each)
    ((float4*)(smem + SM_CN))[tid]       = ((const float4*)g_cnorm)[tid];
    ((float4*)(smem + SM_CN))[tid + 128] = ((const float4*)g_cnorm)[tid + 128];

    // ---- B half-tile 0 (codes 0..63) via cp.async ----
    #pragma unroll
    for (int it = 0; it < 8; it++) {
        int i = it * 128 + tid;            // 0..1023
        int r = i >> 4, c8 = i & 15;
        const __half* src = g_eThi + (size_t)r * DD + c8 * 8;
        cp_async16(sb + SM_B + r * (PAD * 2) + c8 * 16, src);
    }
    cp_commit();
    cp_wait0();
    __syncthreads();

    float va1 = -3.4e38f, va2 = -3.4e38f, vb1 = -3.4e38f, vb2 = -3.4e38f;
    int ia1 = 0, ib1 = 0;
    const int rw = wid * 16;
    const float* cns = (const float*)(smem + SM_CN);

    for (int th = 0; th < 16; th++) {      // 16 half-tiles of 64 codes
        if (th > 0) {
            __syncthreads();   // all warps done reading previous half-tile
            #pragma unroll
            for (int it = 0; it < 8; it++) {
                int i = it * 128 + tid;
                int r = i >> 4, c8 = i & 15;
                const __half* src = g_eThi + (size_t)(th * 64 + r) * DD + c8 * 8;
                cp_async16(sb + SM_B + r * (PAD * 2) + c8 * 16, src);
            }
            cp_commit();
            cp_wait0();
            __syncthreads();
        }

        const char* Bhi = smem + SM_B;
        const char* Ahi = smem + SM_A;
        const int code0 = th * 64;         // global code base of this half-tile

        float acc[8][4];
        #pragma unroll
        for (int f = 0; f < 8; f++) {
            float c0 = -0.5f * cns[code0 + f * 8 + tg * 2];
            float c1 = -0.5f * cns[code0 + f * 8 + tg * 2 + 1];
            acc[f][0] = c0; acc[f][1] = c1; acc[f][2] = c0; acc[f][3] = c1;
        }

        #pragma unroll
        for (int k = 0; k < 8; k++) {
            int ca = k * 16 + tg * 2;
            int oa0 = (rw + g) * (PAD * 2) + ca * 2;
            int oa1 = (rw + g + 8) * (PAD * 2) + ca * 2;
            uint32_t ah0 = *(const uint32_t*)(Ahi + oa0);
            uint32_t ah1 = *(const uint32_t*)(Ahi + oa1);
            uint32_t ah2 = *(const uint32_t*)(Ahi + oa0 + 16);
            uint32_t ah3 = *(const uint32_t*)(Ahi + oa1 + 16);
            #pragma unroll
            for (int f = 0; f < 8; f++) {
                int ob = (f * 8 + g) * (PAD * 2) + ca * 2;
                uint32_t bh0 = *(const uint32_t*)(Bhi + ob);
                uint32_t bh1 = *(const uint32_t*)(Bhi + ob + 16);
                mma_f16(acc[f][0], acc[f][1], acc[f][2], acc[f][3],
                        ah0, ah1, ah2, ah3, bh0, bh1);
            }
        }

        #pragma unroll
        for (int f = 0; f < 8; f++) {
            int idx0 = code0 + f * 8 + tg * 2;
            float d;
            d = acc[f][0];
            if (d > va1) { va2 = va1; va1 = d; ia1 = idx0; } else if (d > va2) va2 = d;
            d = acc[f][1];
            if (d > va1) { va2 = va1; va1 = d; ia1 = idx0 + 1; } else if (d > va2) va2 = d;
            d = acc[f][2];
            if (d > vb1) { vb2 = vb1; vb1 = d; ib1 = idx0; } else if (d > vb2) vb2 = d;
            d = acc[f][3];
            if (d > vb1) { vb2 = vb1; vb1 = d; ib1 = idx0 + 1; } else if (d > vb2) vb2 = d;
        }
    }

    // reduce across the 4 tg-lanes sharing each row
    #pragma unroll
    for (int off = 2; off; off >>= 1) {
        float ov1 = __shfl_down_sync(0xffffffffu, va1, off, 4);
        int   oi1 = __shfl_down_sync(0xffffffffu, ia1, off, 4);
        float ov2 = __shfl_down_sync(0xffffffffu, va2, off, 4);
        if (ov1 > va1 || (ov1 == va1 && oi1 < ia1)) {
            va2 = fmaxf(va1, ov2); va1 = ov1; ia1 = oi1;
        } else va2 = fmaxf(va2, ov1);
        ov1 = __shfl_down_sync(0xffffffffu, vb1, off, 4);
        oi1 = __shfl_down_sync(0xffffffffu, ib1, off, 4);
        ov2 = __shfl_down_sync(0xffffffffu, vb2, off, 4);
        if (ov1 > vb1 || (ov1 == vb1 && oi1 < ib1)) {
            vb2 = fmaxf(vb1, ov2); vb1 = ov1; ib1 = oi1;
        } else vb2 = fmaxf(vb2, ov1);
    }
    if (tg == 0) {
        int ra = row0 + rw + g, rb = ra + 8;
        g_idx[ra] = ia1;
        g_idx[rb] = ib1;
        if (va1 - va2 < TAU_D) {
            int s = atomicAdd(&g_nflag, 1); g_flag[s] = ra; g_best[ra] = ~0ull;
        }
        if (vb1 - vb2 < TAU_D) {
            int s = atomicAdd(&g_nflag, 1); g_flag[s] = rb; g_best[rb] = ~0ull;
        }
    }
}

// ---------------- tiled exact fp32 rescore of flagged rows ----------------
__global__ void __launch_bounds__(256)
rescore_kernel(const float* __restrict__ x) {
    __shared__ float xs[32 * 128];
    __shared__ int rows[32];
    int tid = threadIdx.x;
    int nflag = min(g_nflag, NR);
    int ntask = ((nflag + 31) >> 5) << 3;
    for (int task = blockIdx.x; task < ntask; task += gridDim.x) {
        int chunk = task >> 3, kt = task & 7;
        int base = chunk * 32;
        int cnt = min(32, nflag - base);
        __syncthreads();
        if (tid < cnt) rows[tid] = g_flag[base + tid];
        __syncthreads();
        for (int i = tid; i < cnt * 32; i += 256)
            ((float4*)xs)[i] = *(const float4*)(x + (size_t)rows[i >> 5] * DD + (i & 31) * 4);
        __syncthreads();

        int code = kt * 128 + (tid & 127);
        int r0 = (tid >> 7) * 16;
        const float4* e4 = (const float4*)(g_eT + (size_t)code * DD);
        float cn = g_cnorm[code];
        float s[16];
        #pragma unroll
        for (int i = 0; i < 16; i++) s[i] = 0.f;
        #pragma unroll 4
        for (int d4 = 0; d4 < 32; d4++) {
            float4 e = e4[d4];
            const float4* xr = ((const float4*)xs) + r0 * 32 + d4;
            #pragma unroll
            for (int i = 0; i < 16; i++) {
                float4 xv = xr[i * 32];
                s[i] = fmaf(e.x, xv.x, s[i]);
                s[i] = fmaf(e.y, xv.y, s[i]);
                s[i] = fmaf(e.z, xv.z, s[i]);
                s[i] = fmaf(e.w, xv.w, s[i]);
            }
        }
        #pragma unroll
        for (int i = 0; i < 16; i++) {
            int r = r0 + i;
            if (r < cnt) {
                float dist = fmaf(-2.f, s[i], cn);
                unsigned u = __float_as_uint(dist);
                u ^= (u >> 31) ? 0xFFFFFFFFu : 0x80000000u;
                ull key = ((ull)u << 32) | (unsigned)code;
                atomicMin(&g_best[rows[r]], key);
            }
        }
    }
}

__global__ void fix_kernel() {
    int i = blockIdx.x * 256 + threadIdx.x;
    if (i < g_nflag && i < NR) {
        int row = g_flag[i];
        g_idx[row] = (int)(g_best[row] & 0xFFFFFFFFu);
    }
}

// ---------------- gather q_st, loss, segment sums (vector red) ----------------
__global__ void scatter_kernel(const float* __restrict__ x, float* __restrict__ outq) {
    int gid = blockIdx.x * 256 + threadIdx.x;
    int n = gid >> 5, dq = gid & 31, d0 = dq * 4;
    int k = g_idx[n];
    float4 xv = *(const float4*)(x + (size_t)n * DD + d0);
    float4 qv = *(const float4*)(g_eT + (size_t)k * DD + d0);
    float r0 = qv.x - xv.x, r1 = qv.y - xv.y, r2 = qv.z - xv.z, r3 = qv.w - xv.w;
    float4 o = make_float4(xv.x + r0, xv.y + r1, xv.z + r2, xv.w + r3);
    *(float4*)(outq + (size_t)n * DD + d0) = o;
    float ls = r0 * r0 + r1 * r1 + r2 * r2 + r3 * r3;

    red_v4(&g_sums[(size_t)k * DD + d0], xv.x, xv.y, xv.z, xv.w);
    if (dq == 0) atomicAdd(&g_count[k], 1.0f);

    __shared__ float wsum[8];
    #pragma unroll
    for (int off = 16; off; off >>= 1) ls += __shfl_down_sync(0xffffffffu, ls, off);
    if ((threadIdx.x & 31) == 0) wsum[threadIdx.x >> 5] = ls;
    __syncthreads();
    if (threadIdx.x < 8) {
        float t = wsum[threadIdx.x];
        #pragma unroll
        for (int off = 4; off; off >>= 1) t += __shfl_down_sync(0xffu, t, off);
        if (threadIdx.x == 0) atomicAdd(&g_lossb[blockIdx.x & 255], t);
    }
}

// ---------------- EMA finalize + loss ----------------
__global__ void finalize_kernel(const float* __restrict__ ema_count,
                                const float* __restrict__ emb_sum,
                                float* __restrict__ out, long long out_size) {
    long long base_q = (long long)NR * DD;
    if (out_size < base_q + 2LL * DD * KK + KK + 1) return;
    int i = blockIdx.x * 256 + threadIdx.x;
    float* out_emb  = out + base_q;
    float* out_cnt  = out_emb + DD * KK;
    float* out_sum  = out_cnt + KK;
    float* out_loss = out_sum + DD * KK;
    if (i < DD * KK) {
        int k = i & (KK - 1);
        int d = i >> 10;                    // i = d*KK + k
        float cnt = 0.15f * ema_count[k] + 0.85f * g_count[k];
        float s   = 0.15f * emb_sum[i]   + 0.85f * g_sums[(size_t)k * DD + d];
        out_sum[i] = s;
        out_emb[i] = s / fmaxf(cnt, 1e-5f);
    }
    if (i < KK) out_cnt[i] = 0.15f * ema_count[i] + 0.85f * g_count[i];
    if (i == 0) {
        float t = 0.f;
        for (int b = 0; b < 256; b++) t += g_lossb[b];
        *out_loss = t * (1.0f / ((float)NR * (float)DD));
    }
}

extern "C" void kernel_launch(void* const* d_in, const int* in_sizes, int n_in,
                              void* d_out, int out_size) {
    const float* x         = (const float*)d_in[0];
    const float* emb       = (const float*)d_in[1];
    const float* ema_count = (const float*)d_in[2];
    const float* emb_sum   = (const float*)d_in[3];
    float* out = (float*)d_out;

    cudaFuncSetAttribute(argmin_mma_kernel,
                         cudaFuncAttributeMaxDynamicSharedMemorySize, SM_TOTAL);

    zero_kernel<<<(KK * DD + 255) / 256, 256>>>();
    transpose_kernel<<<dim3(KK / 32, DD / 32), dim3(32, 8)>>>(emb);
    cnorm_kernel<<<KK / 256, 256>>>(emb);
    argmin_mma_kernel<<<NR / TM, 128, SM_TOTAL>>>(x);
    rescore_kernel<<<1024, 256>>>(x);
    fix_kernel<<<NR / 256, 256>>>();
    scatter_kernel<<<(NR * 32) / 256, 256>>>(x, out);
    finalize_kernel<<<(DD * KK + 255) / 256, 256>>>(ema_count, emb_sum, out,
                                                    (long long)out_size);
}

// round 17
// speedup vs baseline: 1.7413x; 1.0621x over previous
#include <cuda_runtime.h>
#include <cuda_fp16.h>
#include <cstdint>

#define NR 131072
#define DD 128
#define KK 1024
#define TM 64                   // rows per block (4 warps x 16 rows)
#define PAD 136                 // fp16 elems per padded row (272 B)

typedef unsigned long long ull;

// ---------------- device scratch (static; no runtime alloc) ----------------
__device__ int   g_idx[NR];
__device__ float g_sums[KK * DD];      // [K][D] layout (for vector red)
__device__ float g_count[KK];
__device__ float g_lossb[256];
__device__ float g_eT[KK * DD];        // e^T [K][D] fp32
__device__ __half g_eThi[KK * DD];     // fp16(e - 0.5), [K][D]
__device__ float g_cnorm[KK];
__device__ int   g_nflag;
__device__ int   g_flag[NR];
__device__ ull   g_best[NR];

// ---------------- smem layout (bytes) ----------------
#define ABYTES  17408            /* 64*PAD*2 (hi only) */
#define SM_A    0                /* Ahi : 17408 */
#define SM_B    17408            /* Bhi half-tile (64 codes) : 17408 */
#define SM_CN   34816            /* 1024 fp32 : 4096 */
#define SM_TOTAL 38912

#define TAU_D 0.009f             // flag threshold on D-gap (~9 sigma of x_lo.e'_hi error)

// ---------------- helpers ----------------
__device__ __forceinline__ uint32_t smem_u32(const void* p) {
    uint32_t a;
    asm("{ .reg .u64 t; cvta.to.shared.u64 t, %1; cvt.u32.u64 %0, t; }"
        : "=r"(a) : "l"(p));
    return a;
}
__device__ __forceinline__ void cp_async16(uint32_t dst, const void* src) {
    asm volatile("cp.async.cg.shared.global [%0], [%1], 16;"
                 :: "r"(dst), "l"(src) : "memory");
}
__device__ __forceinline__ void cp_commit() {
    asm volatile("cp.async.commit_group;" ::: "memory");
}
__device__ __forceinline__ void cp_wait0() {
    asm volatile("cp.async.wait_group 0;" ::: "memory");
}
__device__ __forceinline__ void ldsm4(uint32_t& r0, uint32_t& r1, uint32_t& r2,
                                      uint32_t& r3, uint32_t addr) {
    asm volatile("ldmatrix.sync.aligned.m8n8.x4.shared.b16 {%0,%1,%2,%3}, [%4];"
                 : "=r"(r0), "=r"(r1), "=r"(r2), "=r"(r3) : "r"(addr));
}
__device__ __forceinline__ void red_v4(float* ptr, float a, float b, float c, float d) {
    asm volatile("red.global.add.v4.f32 [%0], {%1, %2, %3, %4};"
                 :: "l"(ptr), "f"(a), "f"(b), "f"(c), "f"(d) : "memory");
}
__device__ __forceinline__ void mma_f16(float& d0, float& d1, float& d2, float& d3,
                                        uint32_t a0, uint32_t a1, uint32_t a2, uint32_t a3,
                                        uint32_t b0, uint32_t b1) {
    asm volatile("mma.sync.aligned.m16n8k16.row.col.f32.f16.f16.f32 "
                 "{%0,%1,%2,%3}, {%4,%5,%6,%7}, {%8,%9}, {%0,%1,%2,%3};"
                 : "+f"(d0), "+f"(d1), "+f"(d2), "+f"(d3)
                 : "r"(a0), "r"(a1), "r"(a2), "r"(a3), "r"(b0), "r"(b1));
}

// ---------------- prep kernels ----------------
__global__ void zero_kernel() {
    int i = blockIdx.x * 256 + threadIdx.x;
    if (i < KK * DD) g_sums[i] = 0.f;
    if (i < KK)      g_count[i] = 0.f;
    if (i < 256)     g_lossb[i] = 0.f;
    if (i == 0)      g_nflag = 0;
}

// transpose + centered fp16 split fused
__global__ void transpose_kernel(const float* __restrict__ emb) {
    __shared__ float t[32][33];
    int kb = blockIdx.x * 32, db = blockIdx.y * 32;
    int tx = threadIdx.x, ty = threadIdx.y;
    #pragma unroll
    for (int r = ty; r < 32; r += 8)
        t[r][tx] = emb[(size_t)(db + r) * KK + kb + tx];
    __syncthreads();
    #pragma unroll
    for (int r = ty; r < 32; r += 8) {
        float v = t[tx][r];
        size_t o = (size_t)(kb + r) * DD + db + tx;
        g_eT[o] = v;
        g_eThi[o] = __float2half_rn(v - 0.5f);
    }
}

__global__ void cnorm_kernel(const float* __restrict__ emb) {
    int k = blockIdx.x * 256 + threadIdx.x;
    float s = 0.f;
    #pragma unroll 8
    for (int d = 0; d < DD; d++) {
        float e = emb[(size_t)d * KK + k];
        s = fmaf(e, e, s);
    }
    g_cnorm[k] = s;
}

// ---------------- HMMA fp16 1-pass argmin (128 thr, 5 blocks/SM, ldmatrix) ----------------
// D = xhi.e' - cn/2 (acc init = -cn/2); argmin dist == argmax D (row consts drop).
__global__ void __launch_bounds__(128, 5)
argmin_mma_kernel(const float* __restrict__ x) {
    extern __shared__ __align__(16) char smem[];
    const int tid = threadIdx.x;
    const int wid = tid >> 5, lane = tid & 31;
    const int g = lane >> 2, tg = lane & 3;
    const int m8 = lane >> 3, r8 = lane & 7;
    const int row0 = blockIdx.x * TM;
    const uint32_t sb = smem_u32(smem);

    // ---- A tile: load fp32 x, round to fp16, store padded (hi only) ----
    #pragma unroll
    for (int it = 0; it < 8; it++) {
        int c = it * 128 + tid;            // 0..1023
        int r = c >> 4, c8 = c & 15;
        const float4* src = (const float4*)(x + (size_t)(row0 + r) * DD + c8 * 8);
        float4 a = src[0], b = src[1];
        float vals[8] = {a.x, a.y, a.z, a.w, b.x, b.y, b.z, b.w};
        unsigned hs[8];
        #pragma unroll
        for (int j = 0; j < 8; j++)
            hs[j] = __half_as_ushort(__float2half_rn(vals[j]));
        uint4 ph;
        ph.x = hs[0] | (hs[1] << 16); ph.y = hs[2] | (hs[3] << 16);
        ph.z = hs[4] | (hs[5] << 16); ph.w = hs[6] | (hs[7] << 16);
        int off = r * (PAD * 2) + c8 * 16;
        *(uint4*)(smem + SM_A + off) = ph;
    }
    // cnorm -> smem (1024 floats, 128 threads -> 2 float4 each)
    ((float4*)(smem + SM_CN))[tid]       = ((const float4*)g_cnorm)[tid];
    ((float4*)(smem + SM_CN))[tid + 128] = ((const float4*)g_cnorm)[tid + 128];

    // ---- B half-tile 0 (codes 0..63) via cp.async ----
    #pragma unroll
    for (int it = 0; it < 8; it++) {
        int i = it * 128 + tid;            // 0..1023
        int r = i >> 4, c8 = i & 15;
        const __half* src = g_eThi + (size_t)r * DD + c8 * 8;
        cp_async16(sb + SM_B + r * (PAD * 2) + c8 * 16, src);
    }
    cp_commit();
    cp_wait0();
    __syncthreads();

    float va1 = -3.4e38f, va2 = -3.4e38f, vb1 = -3.4e38f, vb2 = -3.4e38f;
    int ia1 = 0, ib1 = 0;
    const int rw = wid * 16;
    const float* cns = (const float*)(smem + SM_CN);

    // ldmatrix lane offsets (rows 272B apart -> conflict-free; validated R10)
    // A: m0=(rows rw..+7,k0-7) m1=(rows rw+8..+15,k0-7) m2=(rw..,k8-15) m3=(rw+8..,k8-15)
    const uint32_t laneA = (uint32_t)((rw + (m8 & 1) * 8 + r8) * (PAD * 2) + (m8 >> 1) * 16);
    // B: m0=(codes 0-7,k0-7) m1=(codes 0-7,k8-15) m2=(codes 8-15,k0-7) m3=(codes 8-15,k8-15)
    const uint32_t laneB = (uint32_t)(((m8 >> 1) * 8 + r8) * (PAD * 2) + (m8 & 1) * 16);

    for (int th = 0; th < 16; th++) {      // 16 half-tiles of 64 codes
        if (th > 0) {
            __syncthreads();   // all warps done reading previous half-tile
            #pragma unroll
            for (int it = 0; it < 8; it++) {
                int i = it * 128 + tid;
                int r = i >> 4, c8 = i & 15;
                const __half* src = g_eThi + (size_t)(th * 64 + r) * DD + c8 * 8;
                cp_async16(sb + SM_B + r * (PAD * 2) + c8 * 16, src);
            }
            cp_commit();
            cp_wait0();
            __syncthreads();
        }

        const uint32_t aaHi = sb + SM_A + laneA;
        const uint32_t bbB  = sb + SM_B + laneB;
        const int code0 = th * 64;         // global code base of this half-tile

        float acc[8][4];
        #pragma unroll
        for (int f = 0; f < 8; f++) {
            float c0 = -0.5f * cns[code0 + f * 8 + tg * 2];
            float c1 = -0.5f * cns[code0 + f * 8 + tg * 2 + 1];
            acc[f][0] = c0; acc[f][1] = c1; acc[f][2] = c0; acc[f][3] = c1;
        }

        #pragma unroll
        for (int k = 0; k < 8; k++) {
            uint32_t ah0, ah1, ah2, ah3;
            ldsm4(ah0, ah1, ah2, ah3, aaHi + k * 32);
            #pragma unroll
            for (int p2 = 0; p2 < 4; p2++) {
                uint32_t bh0, bh1, bh2, bh3;
                ldsm4(bh0, bh1, bh2, bh3, bbB + p2 * (16 * PAD * 2) + k * 32);
                mma_f16(acc[p2 * 2][0], acc[p2 * 2][1], acc[p2 * 2][2], acc[p2 * 2][3],
                        ah0, ah1, ah2, ah3, bh0, bh1);
                mma_f16(acc[p2 * 2 + 1][0], acc[p2 * 2 + 1][1],
                        acc[p2 * 2 + 1][2], acc[p2 * 2 + 1][3],
                        ah0, ah1, ah2, ah3, bh2, bh3);
            }
        }

        #pragma unroll
        for (int f = 0; f < 8; f++) {
            int idx0 = code0 + f * 8 + tg * 2;
            float d;
            d = acc[f][0];
            if (d > va1) { va2 = va1; va1 = d; ia1 = idx0; } else if (d > va2) va2 = d;
            d = acc[f][1];
            if (d > va1) { va2 = va1; va1 = d; ia1 = idx0 + 1; } else if (d > va2) va2 = d;
            d = acc[f][2];
            if (d > vb1) { vb2 = vb1; vb1 = d; ib1 = idx0; } else if (d > vb2) vb2 = d;
            d = acc[f][3];
            if (d > vb1) { vb2 = vb1; vb1 = d; ib1 = idx0 + 1; } else if (d > vb2) vb2 = d;
        }
    }

    // reduce across the 4 tg-lanes sharing each row
    #pragma unroll
    for (int off = 2; off; off >>= 1) {
        float ov1 = __shfl_down_sync(0xffffffffu, va1, off, 4);
        int   oi1 = __shfl_down_sync(0xffffffffu, ia1, off, 4);
        float ov2 = __shfl_down_sync(0xffffffffu, va2, off, 4);
        if (ov1 > va1 || (ov1 == va1 && oi1 < ia1)) {
            va2 = fmaxf(va1, ov2); va1 = ov1; ia1 = oi1;
        } else va2 = fmaxf(va2, ov1);
        ov1 = __shfl_down_sync(0xffffffffu, vb1, off, 4);
        oi1 = __shfl_down_sync(0xffffffffu, ib1, off, 4);
        ov2 = __shfl_down_sync(0xffffffffu, vb2, off, 4);
        if (ov1 > vb1 || (ov1 == vb1 && oi1 < ib1)) {
            vb2 = fmaxf(vb1, ov2); vb1 = ov1; ib1 = oi1;
        } else vb2 = fmaxf(vb2, ov1);
    }
    if (tg == 0) {
        int ra = row0 + rw + g, rb = ra + 8;
        g_idx[ra] = ia1;
        g_idx[rb] = ib1;
        if (va1 - va2 < TAU_D) {
            int s = atomicAdd(&g_nflag, 1); g_flag[s] = ra; g_best[ra] = ~0ull;
        }
        if (vb1 - vb2 < TAU_D) {
            int s = atomicAdd(&g_nflag, 1); g_flag[s] = rb; g_best[rb] = ~0ull;
        }
    }
}

// ---------------- tiled exact fp32 rescore of flagged rows ----------------
__global__ void __launch_bounds__(256)
rescore_kernel(const float* __restrict__ x) {
    __shared__ float xs[32 * 128];
    __shared__ int rows[32];
    int tid = threadIdx.x;
    int nflag = min(g_nflag, NR);
    int ntask = ((nflag + 31) >> 5) << 3;
    for (int task = blockIdx.x; task < ntask; task += gridDim.x) {
        int chunk = task >> 3, kt = task & 7;
        int base = chunk * 32;
        int cnt = min(32, nflag - base);
        __syncthreads();
        if (tid < cnt) rows[tid] = g_flag[base + tid];
        __syncthreads();
        for (int i = tid; i < cnt * 32; i += 256)
            ((float4*)xs)[i] = *(const float4*)(x + (size_t)rows[i >> 5] * DD + (i & 31) * 4);
        __syncthreads();

        int code = kt * 128 + (tid & 127);
        int r0 = (tid >> 7) * 16;
        const float4* e4 = (const float4*)(g_eT + (size_t)code * DD);
        float cn = g_cnorm[code];
        float s[16];
        #pragma unroll
        for (int i = 0; i < 16; i++) s[i] = 0.f;
        #pragma unroll 4
        for (int d4 = 0; d4 < 32; d4++) {
            float4 e = e4[d4];
            const float4* xr = ((const float4*)xs) + r0 * 32 + d4;
            #pragma unroll
            for (int i = 0; i < 16; i++) {
                float4 xv = xr[i * 32];
                s[i] = fmaf(e.x, xv.x, s[i]);
                s[i] = fmaf(e.y, xv.y, s[i]);
                s[i] = fmaf(e.z, xv.z, s[i]);
                s[i] = fmaf(e.w, xv.w, s[i]);
            }
        }
        #pragma unroll
        for (int i = 0; i < 16; i++) {
            int r = r0 + i;
            if (r < cnt) {
                float dist = fmaf(-2.f, s[i], cn);
                unsigned u = __float_as_uint(dist);
                u ^= (u >> 31) ? 0xFFFFFFFFu : 0x80000000u;
                ull key = ((ull)u << 32) | (unsigned)code;
                atomicMin(&g_best[rows[r]], key);
            }
        }
    }
}

__global__ void fix_kernel() {
    int i = blockIdx.x * 256 + threadIdx.x;
    if (i < g_nflag && i < NR) {
        int row = g_flag[i];
        g_idx[row] = (int)(g_best[row] & 0xFFFFFFFFu);
    }
}

// ---------------- gather q_st, loss, segment sums (vector red) ----------------
__global__ void scatter_kernel(const float* __restrict__ x, float* __restrict__ outq) {
    int gid = blockIdx.x * 256 + threadIdx.x;
    int n = gid >> 5, dq = gid & 31, d0 = dq * 4;
    int k = g_idx[n];
    float4 xv = *(const float4*)(x + (size_t)n * DD + d0);
    float4 qv = *(const float4*)(g_eT + (size_t)k * DD + d0);
    float r0 = qv.x - xv.x, r1 = qv.y - xv.y, r2 = qv.z - xv.z, r3 = qv.w - xv.w;
    float4 o = make_float4(xv.x + r0, xv.y + r1, xv.z + r2, xv.w + r3);
    *(float4*)(outq + (size_t)n * DD + d0) = o;
    float ls = r0 * r0 + r1 * r1 + r2 * r2 + r3 * r3;

    red_v4(&g_sums[(size_t)k * DD + d0], xv.x, xv.y, xv.z, xv.w);
    if (dq == 0) atomicAdd(&g_count[k], 1.0f);

    __shared__ float wsum[8];
    #pragma unroll
    for (int off = 16; off; off >>= 1) ls += __shfl_down_sync(0xffffffffu, ls, off);
    if ((threadIdx.x & 31) == 0) wsum[threadIdx.x >> 5] = ls;
    __syncthreads();
    if (threadIdx.x < 8) {
        float t = wsum[threadIdx.x];
        #pragma unroll
        for (int off = 4; off; off >>= 1) t += __shfl_down_sync(0xffu, t, off);
        if (threadIdx.x == 0) atomicAdd(&g_lossb[blockIdx.x & 255], t);
    }
}

// ---------------- EMA finalize + loss ----------------
__global__ void finalize_kernel(const float* __restrict__ ema_count,
                                const float* __restrict__ emb_sum,
                                float* __restrict__ out, long long out_size) {
    long long base_q = (long long)NR * DD;
    if (out_size < base_q + 2LL * DD * KK + KK + 1) return;
    int i = blockIdx.x * 256 + threadIdx.x;
    float* out_emb  = out + base_q;
    float* out_cnt  = out_emb + DD * KK;
    float* out_sum  = out_cnt + KK;
    float* out_loss = out_sum + DD * KK;
    if (i < DD * KK) {
        int k = i & (KK - 1);
        int d = i >> 10;                    // i = d*KK + k
        float cnt = 0.15f * ema_count[k] + 0.85f * g_count[k];
        float s   = 0.15f * emb_sum[i]   + 0.85f * g_sums[(size_t)k * DD + d];
        out_sum[i] = s;
        out_emb[i] = s / fmaxf(cnt, 1e-5f);
    }
    if (i < KK) out_cnt[i] = 0.15f * ema_count[i] + 0.85f * g_count[i];
    if (i == 0) {
        float t = 0.f;
        for (int b = 0; b < 256; b++) t += g_lossb[b];
        *out_loss = t * (1.0f / ((float)NR * (float)DD));
    }
}

extern "C" void kernel_launch(void* const* d_in, const int* in_sizes, int n_in,
                              void* d_out, int out_size) {
    const float* x         = (const float*)d_in[0];
    const float* emb       = (const float*)d_in[1];
    const float* ema_count = (const float*)d_in[2];
    const float* emb_sum   = (const float*)d_in[3];
    float* out = (float*)d_out;

    cudaFuncSetAttribute(argmin_mma_kernel,
                         cudaFuncAttributeMaxDynamicSharedMemorySize, SM_TOTAL);

    zero_kernel<<<(KK * DD + 255) / 256, 256>>>();
    transpose_kernel<<<dim3(KK / 32, DD / 32), dim3(32, 8)>>>(emb);
    cnorm_kernel<<<KK / 256, 256>>>(emb);
    argmin_mma_kernel<<<NR / TM, 128, SM_TOTAL>>>(x);
    rescore_kernel<<<1024, 256>>>(x);
    fix_kernel<<<NR / 256, 256>>>();
    scatter_kernel<<<(NR * 32) / 256, 256>>>(x, out);
    finalize_kernel<<<(DD * KK + 255) / 256, 256>>>(ema_count, emb_sum, out,
                                                    (long long)out_size);
}